// round 11
// baseline (speedup 1.0000x reference)
#include <cuda_runtime.h>
#include <cuda_bf16.h>

// Embedding gather: out[token, :] = table[ids[token], :]
// ids: [32*8192] int32, table: [256,256] f32, out: [32*8192, 256] f32.
//
// Final structure: steady-state DRAM-write-roofline-bound (268 MB/launch
// must drain to HBM each replay period; at ~41 us that is ~6.5 TB/s
// sustained writes, ~82% of spec — six structural variants converged here).
// Each block owns one contiguous 16 KB output chunk; each thread runs 4
// independent gather->store chains (k steps 4 KB) with lane-contiguous
// float4 accesses (512 B / 4 L1 lines per warp instruction). ids loads are
// warp-uniform broadcasts; the 256 KB table is L1/L2-resident. Default
// store policy (measured >= .cs). R11: all-32-bit indexing (16.7M float4
// fits in int), removing 64-bit IMAD address chains in front of the memory
// ops.

static constexpr int TOKENS       = 32 * 8192;           // 262144
static constexpr int EMBED        = 256;
static constexpr int VEC_PER_ROW  = EMBED / 4;           // 64 float4 per row
static constexpr int TOTAL_VEC4   = TOKENS * VEC_PER_ROW;// 16,777,216 (< 2^31)
static constexpr int ITEMS        = 4;                   // chains per thread
static constexpr int THREADS      = 256;

__global__ __launch_bounds__(THREADS)
void embed_gather_kernel(const int* __restrict__ ids,
                         const float4* __restrict__ table4,
                         float4* __restrict__ out4)
{
    // Block b owns float4 range [b*1024, (b+1)*1024), k steps by 256 (4 KB).
    const unsigned base = blockIdx.x * (unsigned)(ITEMS * THREADS) + threadIdx.x;

    unsigned g[ITEMS];
    int      tok[ITEMS];
    float4   v[ITEMS];

    // Batched index loads (warp-uniform -> single broadcast L1 hit each).
    #pragma unroll
    for (int k = 0; k < ITEMS; k++) {
        g[k]   = base + (unsigned)(k * THREADS);
        tok[k] = __ldg(&ids[g[k] >> 6]);
    }

    // Batched table loads (4 independent LDG.128; table resident in L1/L2).
    #pragma unroll
    for (int k = 0; k < ITEMS; k++) {
        v[k] = __ldg(&table4[(unsigned)tok[k] * (unsigned)VEC_PER_ROW + (g[k] & 63u)]);
    }

    // Default-policy stores: contiguous 4 KB per block per k-step.
    #pragma unroll
    for (int k = 0; k < ITEMS; k++) {
        out4[g[k]] = v[k];
    }
}

extern "C" void kernel_launch(void* const* d_in, const int* in_sizes, int n_in,
                              void* d_out, int out_size)
{
    const int*   ids   = (const int*)d_in[0];    // [32, 8192] int32
    const float* table = (const float*)d_in[1];  // [256, 256] f32
    float*       out   = (float*)d_out;          // [32, 8192, 256] f32

    const int blocks = TOTAL_VEC4 / (ITEMS * THREADS);   // 16384

    embed_gather_kernel<<<blocks, THREADS>>>(
        ids, (const float4*)table, (float4*)out);
}